// round 15
// baseline (speedup 1.0000x reference)
#include <cuda_runtime.h>
#include <cuda_bf16.h>
#include <cstdint>

// ---------------------------------------------------------------------------
// GraphSAGE 2-layer mean-aggregator forward. (R8 structure, l1 M-tile = 128)
// K1 (prep): m2 = mean10(feats[ids2]) -> bf16 hi/lo; f1/f0 gather-split;
//            m1 = mean25 -> split; W1/W2 split; zero accumulators.
// K2: l1 GEMM M=128 tiles (relu + group-25 mean -> mh1, h1 never stored)
//     + h0 split-K GEMM (M=128, 1 chunk), merged; pure-copy loaders.
// K3: g0 = [relu(h0)@Wx2+bx2 ; mh1@Wn2+bn2]  (split-K atomics)
// K4: out = normalize(g0) @ Wfc + bfc
// All GEMMs: bf16 hi/lo 3-split (Ah*Bh + Ah*Bl + Al*Bh), fp32 accum.
// ---------------------------------------------------------------------------

#define NB     512
#define DIM    256
#define HIDV   128
#define M1ROWS 12800

__device__ __align__(16) __nv_bfloat16 g_m2h[M1ROWS * DIM], g_m2l[M1ROWS * DIM];
__device__ __align__(16) __nv_bfloat16 g_f1h[M1ROWS * DIM], g_f1l[M1ROWS * DIM];
__device__ __align__(16) __nv_bfloat16 g_f0h[NB * DIM],     g_f0l[NB * DIM];
__device__ __align__(16) __nv_bfloat16 g_m1h[NB * DIM],     g_m1l[NB * DIM];
__device__ __align__(16) __nv_bfloat16 g_w1h[2 * DIM * HIDV], g_w1l[2 * DIM * HIDV];
__device__ __align__(16) __nv_bfloat16 g_w2h[2 * DIM * HIDV], g_w2l[2 * DIM * HIDV];
__device__ float g_acc[3 * NB * DIM];   // [0]=mh1, [1]=h0(pre-relu), [2]=g0

// ---------------------------------------------------------------------------
// helpers
// ---------------------------------------------------------------------------
__device__ __forceinline__ uint32_t smem_u32(const void* p) {
    uint32_t a;
    asm("{ .reg .u64 t; cvta.to.shared.u64 t, %1; cvt.u32.u64 %0, t; }" : "=r"(a) : "l"(p));
    return a;
}
__device__ __forceinline__ uint32_t packbf(__nv_bfloat16 a, __nv_bfloat16 b) {
    __nv_bfloat162 t(a, b);
    return *reinterpret_cast<uint32_t*>(&t);
}
__device__ __forceinline__ void split_store(void* ph, void* pl, float4 v) {
    __nv_bfloat16 hx = __float2bfloat16_rn(v.x);
    __nv_bfloat16 hy = __float2bfloat16_rn(v.y);
    __nv_bfloat16 hz = __float2bfloat16_rn(v.z);
    __nv_bfloat16 hw = __float2bfloat16_rn(v.w);
    __nv_bfloat16 lx = __float2bfloat16_rn(v.x - __bfloat162float(hx));
    __nv_bfloat16 ly = __float2bfloat16_rn(v.y - __bfloat162float(hy));
    __nv_bfloat16 lz = __float2bfloat16_rn(v.z - __bfloat162float(hz));
    __nv_bfloat16 lw = __float2bfloat16_rn(v.w - __bfloat162float(hw));
    *reinterpret_cast<uint2*>(ph) = make_uint2(packbf(hx, hy), packbf(hz, hw));
    *reinterpret_cast<uint2*>(pl) = make_uint2(packbf(lx, ly), packbf(lz, lw));
}
__device__ __forceinline__ void ldsm4(uint32_t* r, uint32_t addr) {
    asm volatile("ldmatrix.sync.aligned.m8n8.x4.shared.b16 {%0,%1,%2,%3}, [%4];"
        : "=r"(r[0]), "=r"(r[1]), "=r"(r[2]), "=r"(r[3]) : "r"(addr));
}
__device__ __forceinline__ void ldsm2t(uint32_t* r, uint32_t addr) {
    asm volatile("ldmatrix.sync.aligned.m8n8.x2.trans.shared.b16 {%0,%1}, [%2];"
        : "=r"(r[0]), "=r"(r[1]) : "r"(addr));
}
__device__ __forceinline__ void mma16816(float* d, const uint32_t* a, const uint32_t* b) {
    asm volatile("mma.sync.aligned.m16n8k16.row.col.f32.bf16.bf16.f32 "
        "{%0,%1,%2,%3},{%4,%5,%6,%7},{%8,%9},{%0,%1,%2,%3};"
        : "+f"(d[0]), "+f"(d[1]), "+f"(d[2]), "+f"(d[3])
        : "r"(a[0]), "r"(a[1]), "r"(a[2]), "r"(a[3]), "r"(b[0]), "r"(b[1]));
}

// ---------------------------------------------------------------------------
// K1: prep (verbatim R8). Block roles by blockIdx.x:
//  [0,1600)    m2: warp/row mean-10 gather -> split
//  [1600,3200) f1: warp/row gather feats[ids1] -> split
//  [3200,3264) f0: warp/row gather feats[ids]  -> split
//  [3264,3328) m1: warp/row mean-25 gather -> split
//  [3328,3392) W split
//  [3392,3416) zero g_acc
// ---------------------------------------------------------------------------
__global__ __launch_bounds__(256)
void prep_kernel(const float* __restrict__ feats, const int* __restrict__ ids,
                 const int* __restrict__ ids1, const int* __restrict__ ids2,
                 const float* __restrict__ Wx1, const float* __restrict__ Wn1,
                 const float* __restrict__ Wx2, const float* __restrict__ Wn2)
{
    const int b = blockIdx.x, t = threadIdx.x, w = t >> 5, lane = t & 31;

    if (b < 1600) {                                  // m2 mean-10
        const int row = b * 8 + w;
        float4 a0 = make_float4(0.f, 0.f, 0.f, 0.f), a1 = a0;
        const int* bp = ids2 + (size_t)row * 10;
#pragma unroll
        for (int j = 0; j < 10; ++j) {
            const float4* rp = (const float4*)(feats + (size_t)__ldg(&bp[j]) * DIM);
            float4 v0 = __ldg(rp + lane), v1 = __ldg(rp + lane + 32);
            a0.x += v0.x; a0.y += v0.y; a0.z += v0.z; a0.w += v0.w;
            a1.x += v1.x; a1.y += v1.y; a1.z += v1.z; a1.w += v1.w;
        }
        a0.x *= 0.1f; a0.y *= 0.1f; a0.z *= 0.1f; a0.w *= 0.1f;
        a1.x *= 0.1f; a1.y *= 0.1f; a1.z *= 0.1f; a1.w *= 0.1f;
        size_t o = (size_t)row * DIM + lane * 4;
        split_store(g_m2h + o, g_m2l + o, a0);
        split_store(g_m2h + o + 128, g_m2l + o + 128, a1);
    } else if (b < 3200) {                           // f1 gather-split
        const int row = (b - 1600) * 8 + w;
        const float4* rp = (const float4*)(feats + (size_t)__ldg(&ids1[row]) * DIM);
        float4 v0 = __ldg(rp + lane), v1 = __ldg(rp + lane + 32);
        size_t o = (size_t)row * DIM + lane * 4;
        split_store(g_f1h + o, g_f1l + o, v0);
        split_store(g_f1h + o + 128, g_f1l + o + 128, v1);
    } else if (b < 3264) {                           // f0 gather-split
        const int row = (b - 3200) * 8 + w;
        const float4* rp = (const float4*)(feats + (size_t)__ldg(&ids[row]) * DIM);
        float4 v0 = __ldg(rp + lane), v1 = __ldg(rp + lane + 32);
        size_t o = (size_t)row * DIM + lane * 4;
        split_store(g_f0h + o, g_f0l + o, v0);
        split_store(g_f0h + o + 128, g_f0l + o + 128, v1);
    } else if (b < 3328) {                           // m1 mean-25 -> split
        const int row = (b - 3264) * 8 + w;
        float4 a0 = make_float4(0.f, 0.f, 0.f, 0.f), a1 = a0;
        const int* bp = ids1 + (size_t)row * 25;
#pragma unroll
        for (int j = 0; j < 25; ++j) {
            const float4* rp = (const float4*)(feats + (size_t)__ldg(&bp[j]) * DIM);
            float4 v0 = __ldg(rp + lane), v1 = __ldg(rp + lane + 32);
            a0.x += v0.x; a0.y += v0.y; a0.z += v0.z; a0.w += v0.w;
            a1.x += v1.x; a1.y += v1.y; a1.z += v1.z; a1.w += v1.w;
        }
        const float s = 1.f / 25.f;
        a0.x *= s; a0.y *= s; a0.z *= s; a0.w *= s;
        a1.x *= s; a1.y *= s; a1.z *= s; a1.w *= s;
        size_t o = (size_t)row * DIM + lane * 4;
        split_store(g_m1h + o, g_m1l + o, a0);
        split_store(g_m1h + o + 128, g_m1l + o + 128, a1);
    } else if (b < 3392) {                           // W split
        const int idx = (b - 3328) * 2048 + t * 8;
        const int mat = idx >> 15, off = idx & 32767;
        const float* src = (mat == 0) ? Wx1 : (mat == 1) ? Wn1 : (mat == 2) ? Wx2 : Wn2;
        __nv_bfloat16 *dh, *dl;
        if (mat < 2) { dh = g_w1h + mat * 32768 + off;       dl = g_w1l + mat * 32768 + off; }
        else         { dh = g_w2h + (mat - 2) * 32768 + off; dl = g_w2l + (mat - 2) * 32768 + off; }
        const float4* sp = (const float4*)(src + off);
        float4 v0 = __ldg(sp), v1 = __ldg(sp + 1);
        split_store(dh,     dl,     v0);
        split_store(dh + 4, dl + 4, v1);
    } else {                                         // zero g_acc
        const int basei = (b - 3392) * 16384 + t * 4;
        const float4 z = make_float4(0.f, 0.f, 0.f, 0.f);
#pragma unroll
        for (int q = 0; q < 16; ++q)
            *reinterpret_cast<float4*>(g_acc + basei + q * 1024) = z;
    }
}

// ---------------------------------------------------------------------------
// GEMM tile constants
// ---------------------------------------------------------------------------
#define ASTR    144
#define BSTR    272
#define A128SZ  (128 * ASTR)                  // 18432 (K2: M=128 tile)
#define A64SZ   (64 * ASTR)                   // 9216  (K3: M=64 tile)
#define BSZ     (64 * BSTR)                   // 17408
#define SM_K2   (2 * (A128SZ + BSZ) + 256)    // 71936 (single buffer, occ 2)
#define SM_K3   (2 * (A64SZ + BSZ) + 256)     // 53504

// ---------------------------------------------------------------------------
// K2: merged layer-1 GEMM + h0 GEMM, M=128 tiles, pure-copy loaders.
//  blocks [0,200):  l1 tile: m0=(b>>1)*128, half=b&1; 4 K-chunks;
//                   epilogue relu + group-25 mean -> atomicAdd g_acc[0] (mh1)
//  blocks [200,232): h0 split-K: m0=(bid&3)*128, half=(bid>>2)&1, kz=bid>>3;
//                   1 K-chunk; atomicAdd g_acc[1] (+bias on kz==0)
// Warp layout (R6 gemm_k<.,128> proven): 4x2 warps, 2 M-subtiles x 8 N-tiles.
// ---------------------------------------------------------------------------
__global__ __launch_bounds__(256, 2)
void k2_kernel(const float* __restrict__ bx1, const float* __restrict__ bn1)
{
    extern __shared__ char smraw[];
    uint32_t raw = smem_u32(smraw);
    uint32_t sb  = (raw + 255) & ~255u;
    char* base   = smraw + (sb - raw);

    const int tid = threadIdx.x, wid = tid >> 5, lane = tid & 31;
    const int g = lane >> 2, tg = lane & 3;
    const int b = blockIdx.x;

    const bool is_l1 = (b < 200);
    int m0, half, kz0, nch;
    if (is_l1) {
        m0 = (b >> 1) * 128; half = b & 1; kz0 = 0; nch = 4;
    } else {
        const int bid = b - 200;
        m0 = (bid & 3) * 128; half = (bid >> 2) & 1; kz0 = bid >> 3; nch = 1;
    }
    const __nv_bfloat16* __restrict__ Asrc_h =
        is_l1 ? (half ? g_m2h : g_f1h) : (half ? g_m1h : g_f0h);
    const __nv_bfloat16* __restrict__ Asrc_l =
        is_l1 ? (half ? g_m2l : g_f1l) : (half ? g_m1l : g_f0l);
    const __nv_bfloat16* __restrict__ Wh = g_w1h + half * 32768;
    const __nv_bfloat16* __restrict__ Wl = g_w1l + half * 32768;
    const float* __restrict__ bias = half ? bn1 : bx1;

    // loaders: A 128 rows (2 threads/row), B 64 k-rows (4 threads/row)
    const int ar = tid >> 1, ak0 = (tid & 1) * 32;
    const int krow = tid >> 2, n0 = (tid & 3) * 32;

    char* AhS = base;
    char* AlS = AhS + A128SZ;
    char* BhS = AlS + A128SZ;
    char* BlS = BhS + BSZ;

    auto load_chunk = [&](int c) {
        size_t asrc = (size_t)(m0 + ar) * DIM + c * 64 + ak0;
        uint32_t ad = (uint32_t)ar * ASTR + (uint32_t)ak0 * 2;
#pragma unroll
        for (int q = 0; q < 4; ++q) {
            *(uint4*)(AhS + ad + q * 16) = __ldg((const uint4*)(Asrc_h + asrc + q * 8));
            *(uint4*)(AlS + ad + q * 16) = __ldg((const uint4*)(Asrc_l + asrc + q * 8));
        }
        size_t bsrc = (size_t)(c * 64 + krow) * HIDV + n0;
        uint32_t bd = (uint32_t)krow * BSTR + (uint32_t)n0 * 2;
#pragma unroll
        for (int q = 0; q < 4; ++q) {
            *(uint4*)(BhS + bd + q * 16) = __ldg((const uint4*)(Wh + bsrc + q * 8));
            *(uint4*)(BlS + bd + q * 16) = __ldg((const uint4*)(Wl + bsrc + q * 8));
        }
    };

    const int wm  = (wid & 3) * 32;      // 2 M-subtiles of 16
    const int wnl = (wid >> 2) * 64;     // 8 N-tiles of 8
    float acc[2][8][4];
#pragma unroll
    for (int mt = 0; mt < 2; ++mt)
#pragma unroll
        for (int nt = 0; nt < 8; ++nt)
#pragma unroll
            for (int i = 0; i < 4; ++i) acc[mt][nt][i] = 0.f;

    auto mma_chunk = [&]() {
        const uint32_t Ab = sb, Bb = sb + 2 * A128SZ;
#pragma unroll
        for (int ks = 0; ks < 4; ++ks) {
            const int k0 = ks * 16;
            uint32_t ah[2][4], al[2][4];
#pragma unroll
            for (int mt = 0; mt < 2; ++mt) {
                uint32_t ra = Ab + (uint32_t)(wm + mt * 16 + (lane & 15)) * ASTR
                            + (uint32_t)(lane >> 4) * 16 + (uint32_t)k0 * 2;
                ldsm4(ah[mt], ra);
                ldsm4(al[mt], ra + A128SZ);
            }
            uint32_t bhf[8][2], blf[8][2];
#pragma unroll
            for (int nt = 0; nt < 8; ++nt) {
                uint32_t rb = Bb + (uint32_t)(k0 + (lane & 15)) * BSTR
                            + (uint32_t)(wnl + nt * 8) * 2;
                ldsm2t(bhf[nt], rb);
                ldsm2t(blf[nt], rb + BSZ);
            }
#pragma unroll
            for (int nt = 0; nt < 8; ++nt)
#pragma unroll
                for (int mt = 0; mt < 2; ++mt) mma16816(acc[mt][nt], ah[mt], bhf[nt]);
#pragma unroll
            for (int nt = 0; nt < 8; ++nt)
#pragma unroll
                for (int mt = 0; mt < 2; ++mt) mma16816(acc[mt][nt], ah[mt], blf[nt]);
#pragma unroll
            for (int nt = 0; nt < 8; ++nt)
#pragma unroll
                for (int mt = 0; mt < 2; ++mt) mma16816(acc[mt][nt], al[mt], bhf[nt]);
        }
    };

#pragma unroll 1
    for (int ci = 0; ci < nch; ++ci) {
        load_chunk(kz0 + ci);
        __syncthreads();
        mma_chunk();
        __syncthreads();
    }

    if (is_l1) {
        // relu + bias -> smem stage (128 x 130 fp32 = 66560 B, fits in 71936)
        float* ep = (float*)base;
#pragma unroll
        for (int mt = 0; mt < 2; ++mt)
#pragma unroll
            for (int nt = 0; nt < 8; ++nt) {
                int c0 = wnl + nt * 8 + 2 * tg;
                float2 bv = *(const float2*)(bias + c0);
                int r0 = wm + mt * 16 + g;
                ep[r0 * 130 + c0]           = fmaxf(acc[mt][nt][0] + bv.x, 0.f);
                ep[r0 * 130 + c0 + 1]       = fmaxf(acc[mt][nt][1] + bv.y, 0.f);
                ep[(r0 + 8) * 130 + c0]     = fmaxf(acc[mt][nt][2] + bv.x, 0.f);
                ep[(r0 + 8) * 130 + c0 + 1] = fmaxf(acc[mt][nt][3] + bv.y, 0.f);
            }
        __syncthreads();
        const int gbase = m0 / 25;
        for (int idx = tid; idx < 7 * 128; idx += 256) {
            int gi = idx >> 7, col = idx & 127;
            int gg = gbase + gi;
            int rs = gg * 25 - m0;      if (rs < 0)   rs = 0;
            int re = gg * 25 + 25 - m0; if (re > 128) re = 128;
            if (rs < re) {
                float s = 0.f;
                for (int r = rs; r < re; ++r) s += ep[r * 130 + col];
                atomicAdd(&g_acc[(size_t)gg * DIM + half * HIDV + col], s * (1.f / 25.f));
            }
        }
    } else {
        float* h0p = g_acc + NB * DIM;
#pragma unroll
        for (int mt = 0; mt < 2; ++mt)
#pragma unroll
            for (int nt = 0; nt < 8; ++nt) {
                int c0 = wnl + nt * 8 + 2 * tg;
                float bvx = 0.f, bvy = 0.f;
                if (kz0 == 0) { float2 bv = *(const float2*)(bias + c0); bvx = bv.x; bvy = bv.y; }
                int r0 = m0 + wm + mt * 16 + g;
                float* d0 = &h0p[(size_t)r0 * DIM + half * HIDV + c0];
                atomicAdd(d0,     acc[mt][nt][0] + bvx);
                atomicAdd(d0 + 1, acc[mt][nt][1] + bvy);
                float* d1 = &h0p[(size_t)(r0 + 8) * DIM + half * HIDV + c0];
                atomicAdd(d1,     acc[mt][nt][2] + bvx);
                atomicAdd(d1 + 1, acc[mt][nt][3] + bvy);
            }
    }
}

// ---------------------------------------------------------------------------
// K3: g0 = [relu(h0)@Wx2+bx2 ; mh1@Wn2+bn2], split-K (8,2,4). Verbatim R8.
// ---------------------------------------------------------------------------
__global__ __launch_bounds__(256)
void g0_kernel(const float* __restrict__ bx2, const float* __restrict__ bn2)
{
    extern __shared__ char smraw[];
    uint32_t raw = smem_u32(smraw);
    uint32_t sb  = (raw + 255) & ~255u;
    char* base   = smraw + (sb - raw);
    char* AhS = base;
    char* AlS = AhS + A64SZ;
    char* BhS = AlS + A64SZ;
    char* BlS = BhS + BSZ;

    const int tid = threadIdx.x, wid = tid >> 5, lane = tid & 31;
    const int g = lane >> 2, tg = lane & 3;
    const int m0 = blockIdx.x * 64;
    const int half = blockIdx.y;
    const int kz   = blockIdx.z;
    const float* __restrict__ Asrc = half ? g_acc : (g_acc + NB * DIM); // mh1 : h0
    const __nv_bfloat16* __restrict__ Wh = g_w2h + half * 32768;
    const __nv_bfloat16* __restrict__ Wl = g_w2l + half * 32768;
    const float* __restrict__ bias = half ? bn2 : bx2;

    {   // A: fp32 -> split (relu for half 0)
        const int ar = tid >> 2, k0e = (tid & 3) * 16;
        const float4* p = (const float4*)(Asrc + (size_t)(m0 + ar) * DIM + kz * 64 + k0e);
#pragma unroll
        for (int q = 0; q < 4; ++q) {
            float4 v = __ldg(p + q);
            if (half == 0) {
                v.x = fmaxf(v.x, 0.f); v.y = fmaxf(v.y, 0.f);
                v.z = fmaxf(v.z, 0.f); v.w = fmaxf(v.w, 0.f);
            }
            uint32_t o = (uint32_t)ar * ASTR + (uint32_t)(k0e + q * 4) * 2;
            split_store(AhS + o, AlS + o, v);
        }
    }
    {   // B: pure copies
        const int krow = tid >> 2, n0 = (tid & 3) * 32;
        size_t bsrc = (size_t)(kz * 64 + krow) * HIDV + n0;
        uint32_t bd = (uint32_t)krow * BSTR + (uint32_t)n0 * 2;
#pragma unroll
        for (int q = 0; q < 4; ++q) {
            *(uint4*)(BhS + bd + q * 16) = __ldg((const uint4*)(Wh + bsrc + q * 8));
            *(uint4*)(BlS + bd + q * 16) = __ldg((const uint4*)(Wl + bsrc + q * 8));
        }
    }
    __syncthreads();

    const int wm  = (wid & 3) * 16;
    const int wnl = (wid >> 2) * 64;
    float acc[8][4];
#pragma unroll
    for (int nt = 0; nt < 8; ++nt)
#pragma unroll
        for (int i = 0; i < 4; ++i) acc[nt][i] = 0.f;

    const uint32_t Ab = sb, Bb = sb + 2 * A64SZ;
#pragma unroll
    for (int ks = 0; ks < 4; ++ks) {
        const int k0 = ks * 16;
        uint32_t ah[4], al[4];
        uint32_t ra = Ab + (uint32_t)(wm + (lane & 15)) * ASTR
                    + (uint32_t)(lane >> 4) * 16 + (uint32_t)k0 * 2;
        ldsm4(ah, ra);
        ldsm4(al, ra + A64SZ);
        uint32_t bhf[8][2], blf[8][2];
#pragma unroll
        for (int nt = 0; nt < 8; ++nt) {
            uint32_t rb = Bb + (uint32_t)(k0 + (lane & 15)) * BSTR
                        + (uint32_t)(wnl + nt * 8) * 2;
            ldsm2t(bhf[nt], rb);
            ldsm2t(blf[nt], rb + BSZ);
        }
#pragma unroll
        for (int nt = 0; nt < 8; ++nt) mma16816(acc[nt], ah, bhf[nt]);
#pragma unroll
        for (int nt = 0; nt < 8; ++nt) mma16816(acc[nt], ah, blf[nt]);
#pragma unroll
        for (int nt = 0; nt < 8; ++nt) mma16816(acc[nt], al, bhf[nt]);
    }

    float* g0p = g_acc + 2 * NB * DIM;
#pragma unroll
    for (int nt = 0; nt < 8; ++nt) {
        int c0 = wnl + nt * 8 + 2 * tg;
        float bvx = 0.f, bvy = 0.f;
        if (kz == 0) { float2 bv = *(const float2*)(bias + c0); bvx = bv.x; bvy = bv.y; }
        int r0 = m0 + wm + g;
        float* d0 = &g0p[(size_t)r0 * DIM + half * HIDV + c0];
        atomicAdd(d0,     acc[nt][0] + bvx);
        atomicAdd(d0 + 1, acc[nt][1] + bvy);
        float* d1 = &g0p[(size_t)(r0 + 8) * DIM + half * HIDV + c0];
        atomicAdd(d1,     acc[nt][2] + bvx);
        atomicAdd(d1 + 1, acc[nt][3] + bvy);
    }
}

// ---------------------------------------------------------------------------
// K4: row-normalize g0 then FC [256 -> 7]. Verbatim R8.
// ---------------------------------------------------------------------------
__global__ __launch_bounds__(256)
void final_kernel(const float* __restrict__ Wfc, const float* __restrict__ bfc,
                  float* __restrict__ out)
{
    const int row = blockIdx.x;
    __shared__ float s[DIM];
    __shared__ float red[8];
    __shared__ float s_inv;
    const int t = threadIdx.x;
    const float* g0p = g_acc + 2 * NB * DIM;

    float v = g0p[(size_t)row * DIM + t];
    s[t] = v;
    float sq = v * v;
#pragma unroll
    for (int o = 16; o; o >>= 1) sq += __shfl_xor_sync(0xFFFFFFFFu, sq, o);
    if ((t & 31) == 0) red[t >> 5] = sq;
    __syncthreads();
    if (t == 0) {
        float tot = 0.f;
#pragma unroll
        for (int i = 0; i < 8; ++i) tot += red[i];
        s_inv = 1.f / fmaxf(sqrtf(tot), 1e-12f);
    }
    __syncthreads();
    const float inv = s_inv;

    const int w = t >> 5, l = t & 31;
    if (w < 7) {
        float acc = 0.f;
#pragma unroll
        for (int k = l; k < DIM; k += 32)
            acc = fmaf(s[k], __ldg(&Wfc[k * 7 + w]), acc);
#pragma unroll
        for (int o = 16; o; o >>= 1) acc += __shfl_xor_sync(0xFFFFFFFFu, acc, o);
        if (l == 0) out[row * 7 + w] = acc * inv + bfc[w];
    }
}

// ---------------------------------------------------------------------------
extern "C" void kernel_launch(void* const* d_in, const int* in_sizes, int n_in,
                              void* d_out, int out_size)
{
    const int*   ids   = (const int*)  d_in[0];
    const int*   ids1  = (const int*)  d_in[1];
    const int*   ids2  = (const int*)  d_in[2];
    const float* feats = (const float*)d_in[3];
    const float* Wx1   = (const float*)d_in[4];
    const float* bx1   = (const float*)d_in[5];
    const float* Wn1   = (const float*)d_in[6];
    const float* bn1   = (const float*)d_in[7];
    const float* Wx2   = (const float*)d_in[8];
    const float* bx2   = (const float*)d_in[9];
    const float* Wn2   = (const float*)d_in[10];
    const float* bn2   = (const float*)d_in[11];
    const float* Wfc   = (const float*)d_in[12];
    const float* bfc   = (const float*)d_in[13];
    float* out = (float*)d_out;

    cudaFuncSetAttribute(k2_kernel, cudaFuncAttributeMaxDynamicSharedMemorySize, SM_K2);
    cudaFuncSetAttribute(g0_kernel, cudaFuncAttributeMaxDynamicSharedMemorySize, SM_K3);

    // K1: all gathers/means/splits + zeroing (verbatim R8)
    prep_kernel<<<3416, 256>>>(feats, ids, ids1, ids2, Wx1, Wn1, Wx2, Wn2);
    // K2: l1 GEMM M=128 (-> mh1) + h0 GEMM M=128 split-K (merged)
    k2_kernel<<<232, 256, SM_K2>>>(bx1, bn1);
    // K3: g0 GEMM
    g0_kernel<<<dim3(8, 2, 4), 256, SM_K3>>>(bx2, bn2);
    // K4: normalize + FC
    final_kernel<<<NB, 256>>>(Wfc, bfc, out);
}

// round 16
// speedup vs baseline: 1.0359x; 1.0359x over previous
#include <cuda_runtime.h>
#include <cuda_bf16.h>
#include <cstdint>

// ---------------------------------------------------------------------------
// GraphSAGE 2-layer mean-aggregator forward. (exact R8 configuration — the
// measured session best at 65.9us; R11/R12/R14/R15 perturbations all regressed)
// K1 (prep): m2 = mean10(feats[ids2]) -> bf16 hi/lo; f1/f0 gather-split;
//            m1 = mean25 -> split; W1/W2 split; zero accumulators.
// K2: l1 GEMM (relu + group-25 mean -> mh1, h1 never stored) + h0 GEMM,
//     double-buffered smem, M=64 tiles, pure-copy loaders.
// K3: g0 = [relu(h0)@Wx2+bx2 ; mh1@Wn2+bn2]  (split-K atomics)
// K4: out = normalize(g0) @ Wfc + bfc
// All GEMMs: bf16 hi/lo 3-split (Ah*Bh + Ah*Bl + Al*Bh), fp32 accum.
// ---------------------------------------------------------------------------

#define NB     512
#define DIM    256
#define HIDV   128
#define M1ROWS 12800

__device__ __align__(16) __nv_bfloat16 g_m2h[M1ROWS * DIM], g_m2l[M1ROWS * DIM];
__device__ __align__(16) __nv_bfloat16 g_f1h[M1ROWS * DIM], g_f1l[M1ROWS * DIM];
__device__ __align__(16) __nv_bfloat16 g_f0h[NB * DIM],     g_f0l[NB * DIM];
__device__ __align__(16) __nv_bfloat16 g_m1h[NB * DIM],     g_m1l[NB * DIM];
__device__ __align__(16) __nv_bfloat16 g_w1h[2 * DIM * HIDV], g_w1l[2 * DIM * HIDV];
__device__ __align__(16) __nv_bfloat16 g_w2h[2 * DIM * HIDV], g_w2l[2 * DIM * HIDV];
__device__ float g_acc[3 * NB * DIM];   // [0]=mh1, [1]=h0(pre-relu), [2]=g0

// ---------------------------------------------------------------------------
// helpers
// ---------------------------------------------------------------------------
__device__ __forceinline__ uint32_t smem_u32(const void* p) {
    uint32_t a;
    asm("{ .reg .u64 t; cvta.to.shared.u64 t, %1; cvt.u32.u64 %0, t; }" : "=r"(a) : "l"(p));
    return a;
}
__device__ __forceinline__ uint32_t packbf(__nv_bfloat16 a, __nv_bfloat16 b) {
    __nv_bfloat162 t(a, b);
    return *reinterpret_cast<uint32_t*>(&t);
}
__device__ __forceinline__ void split_store(void* ph, void* pl, float4 v) {
    __nv_bfloat16 hx = __float2bfloat16_rn(v.x);
    __nv_bfloat16 hy = __float2bfloat16_rn(v.y);
    __nv_bfloat16 hz = __float2bfloat16_rn(v.z);
    __nv_bfloat16 hw = __float2bfloat16_rn(v.w);
    __nv_bfloat16 lx = __float2bfloat16_rn(v.x - __bfloat162float(hx));
    __nv_bfloat16 ly = __float2bfloat16_rn(v.y - __bfloat162float(hy));
    __nv_bfloat16 lz = __float2bfloat16_rn(v.z - __bfloat162float(hz));
    __nv_bfloat16 lw = __float2bfloat16_rn(v.w - __bfloat162float(hw));
    *reinterpret_cast<uint2*>(ph) = make_uint2(packbf(hx, hy), packbf(hz, hw));
    *reinterpret_cast<uint2*>(pl) = make_uint2(packbf(lx, ly), packbf(lz, lw));
}
__device__ __forceinline__ void ldsm4(uint32_t* r, uint32_t addr) {
    asm volatile("ldmatrix.sync.aligned.m8n8.x4.shared.b16 {%0,%1,%2,%3}, [%4];"
        : "=r"(r[0]), "=r"(r[1]), "=r"(r[2]), "=r"(r[3]) : "r"(addr));
}
__device__ __forceinline__ void ldsm2t(uint32_t* r, uint32_t addr) {
    asm volatile("ldmatrix.sync.aligned.m8n8.x2.trans.shared.b16 {%0,%1}, [%2];"
        : "=r"(r[0]), "=r"(r[1]) : "r"(addr));
}
__device__ __forceinline__ void mma16816(float* d, const uint32_t* a, const uint32_t* b) {
    asm volatile("mma.sync.aligned.m16n8k16.row.col.f32.bf16.bf16.f32 "
        "{%0,%1,%2,%3},{%4,%5,%6,%7},{%8,%9},{%0,%1,%2,%3};"
        : "+f"(d[0]), "+f"(d[1]), "+f"(d[2]), "+f"(d[3])
        : "r"(a[0]), "r"(a[1]), "r"(a[2]), "r"(a[3]), "r"(b[0]), "r"(b[1]));
}

// ---------------------------------------------------------------------------
// K1: prep. Block roles by blockIdx.x:
//  [0,1600)    m2: warp/row mean-10 gather -> split
//  [1600,3200) f1: warp/row gather feats[ids1] -> split
//  [3200,3264) f0: warp/row gather feats[ids]  -> split
//  [3264,3328) m1: warp/row mean-25 gather -> split
//  [3328,3392) W split: Wx1,Wn1,Wx2,Wn2 -> g_w1h/l, g_w2h/l
//  [3392,3416) zero g_acc
// ---------------------------------------------------------------------------
__global__ __launch_bounds__(256)
void prep_kernel(const float* __restrict__ feats, const int* __restrict__ ids,
                 const int* __restrict__ ids1, const int* __restrict__ ids2,
                 const float* __restrict__ Wx1, const float* __restrict__ Wn1,
                 const float* __restrict__ Wx2, const float* __restrict__ Wn2)
{
    const int b = blockIdx.x, t = threadIdx.x, w = t >> 5, lane = t & 31;

    if (b < 1600) {                                  // m2 mean-10
        const int row = b * 8 + w;
        float4 a0 = make_float4(0.f, 0.f, 0.f, 0.f), a1 = a0;
        const int* bp = ids2 + (size_t)row * 10;
#pragma unroll
        for (int j = 0; j < 10; ++j) {
            const float4* rp = (const float4*)(feats + (size_t)__ldg(&bp[j]) * DIM);
            float4 v0 = __ldg(rp + lane), v1 = __ldg(rp + lane + 32);
            a0.x += v0.x; a0.y += v0.y; a0.z += v0.z; a0.w += v0.w;
            a1.x += v1.x; a1.y += v1.y; a1.z += v1.z; a1.w += v1.w;
        }
        a0.x *= 0.1f; a0.y *= 0.1f; a0.z *= 0.1f; a0.w *= 0.1f;
        a1.x *= 0.1f; a1.y *= 0.1f; a1.z *= 0.1f; a1.w *= 0.1f;
        size_t o = (size_t)row * DIM + lane * 4;
        split_store(g_m2h + o, g_m2l + o, a0);
        split_store(g_m2h + o + 128, g_m2l + o + 128, a1);
    } else if (b < 3200) {                           // f1 gather-split
        const int row = (b - 1600) * 8 + w;
        const float4* rp = (const float4*)(feats + (size_t)__ldg(&ids1[row]) * DIM);
        float4 v0 = __ldg(rp + lane), v1 = __ldg(rp + lane + 32);
        size_t o = (size_t)row * DIM + lane * 4;
        split_store(g_f1h + o, g_f1l + o, v0);
        split_store(g_f1h + o + 128, g_f1l + o + 128, v1);
    } else if (b < 3264) {                           // f0 gather-split
        const int row = (b - 3200) * 8 + w;
        const float4* rp = (const float4*)(feats + (size_t)__ldg(&ids[row]) * DIM);
        float4 v0 = __ldg(rp + lane), v1 = __ldg(rp + lane + 32);
        size_t o = (size_t)row * DIM + lane * 4;
        split_store(g_f0h + o, g_f0l + o, v0);
        split_store(g_f0h + o + 128, g_f0l + o + 128, v1);
    } else if (b < 3328) {                           // m1 mean-25 -> split
        const int row = (b - 3264) * 8 + w;
        float4 a0 = make_float4(0.f, 0.f, 0.f, 0.f), a1 = a0;
        const int* bp = ids1 + (size_t)row * 25;
#pragma unroll
        for (int j = 0; j < 25; ++j) {
            const float4* rp = (const float4*)(feats + (size_t)__ldg(&bp[j]) * DIM);
            float4 v0 = __ldg(rp + lane), v1 = __ldg(rp + lane + 32);
            a0.x += v0.x; a0.y += v0.y; a0.z += v0.z; a0.w += v0.w;
            a1.x += v1.x; a1.y += v1.y; a1.z += v1.z; a1.w += v1.w;
        }
        const float s = 1.f / 25.f;
        a0.x *= s; a0.y *= s; a0.z *= s; a0.w *= s;
        a1.x *= s; a1.y *= s; a1.z *= s; a1.w *= s;
        size_t o = (size_t)row * DIM + lane * 4;
        split_store(g_m1h + o, g_m1l + o, a0);
        split_store(g_m1h + o + 128, g_m1l + o + 128, a1);
    } else if (b < 3392) {                           // W split
        const int idx = (b - 3328) * 2048 + t * 8;
        const int mat = idx >> 15, off = idx & 32767;
        const float* src = (mat == 0) ? Wx1 : (mat == 1) ? Wn1 : (mat == 2) ? Wx2 : Wn2;
        __nv_bfloat16 *dh, *dl;
        if (mat < 2) { dh = g_w1h + mat * 32768 + off;       dl = g_w1l + mat * 32768 + off; }
        else         { dh = g_w2h + (mat - 2) * 32768 + off; dl = g_w2l + (mat - 2) * 32768 + off; }
        const float4* sp = (const float4*)(src + off);
        float4 v0 = __ldg(sp), v1 = __ldg(sp + 1);
        split_store(dh,     dl,     v0);
        split_store(dh + 4, dl + 4, v1);
    } else {                                         // zero g_acc
        const int basei = (b - 3392) * 16384 + t * 4;
        const float4 z = make_float4(0.f, 0.f, 0.f, 0.f);
#pragma unroll
        for (int q = 0; q < 16; ++q)
            *reinterpret_cast<float4*>(g_acc + basei + q * 1024) = z;
    }
}

// ---------------------------------------------------------------------------
// GEMM tile constants (M=64 tile, N=128, K-chunk=64)
// ---------------------------------------------------------------------------
#define ASTR   144
#define BSTR   272
#define L1_ASZ (64 * ASTR)                   // 9216
#define L1_BSZ (64 * BSTR)                   // 17408
#define L1_SET (2 * (L1_ASZ + L1_BSZ))       // 53248
#define SM_K2  (2 * L1_SET + 256)            // 106752 (double buffer)
#define SM_K3  (L1_SET + 256)                // 53504  (single buffer)

// ---------------------------------------------------------------------------
// K2: merged layer-1 GEMM + h0 GEMM. Pure-copy loaders from pre-split data.
//  blocks [0,400):  l1 tile: m0=(b>>1)*64, half=b&1; 4 K-chunks;
//                   epilogue relu + group-25 mean -> atomicAdd g_acc[0] (mh1)
//  blocks [400,464): h0 split-K: m0=(bid&7)*64, half=(bid>>3)&1, kz=bid>>4;
//                   1 K-chunk; atomicAdd g_acc[1] (+bias on kz==0)
// ---------------------------------------------------------------------------
__global__ __launch_bounds__(256, 2)
void k2_kernel(const float* __restrict__ bx1, const float* __restrict__ bn1)
{
    extern __shared__ char smraw[];
    uint32_t raw = smem_u32(smraw);
    uint32_t sb  = (raw + 255) & ~255u;
    char* base   = smraw + (sb - raw);

    const int tid = threadIdx.x, wid = tid >> 5, lane = tid & 31;
    const int g = lane >> 2, tg = lane & 3;
    const int b = blockIdx.x;

    const bool is_l1 = (b < 400);
    int m0, half, kz0, nch;
    if (is_l1) {
        m0 = (b >> 1) * 64; half = b & 1; kz0 = 0; nch = 4;
    } else {
        const int bid = b - 400;
        m0 = (bid & 7) * 64; half = (bid >> 3) & 1; kz0 = bid >> 4; nch = 1;
    }
    const __nv_bfloat16* __restrict__ Asrc_h =
        is_l1 ? (half ? g_m2h : g_f1h) : (half ? g_m1h : g_f0h);
    const __nv_bfloat16* __restrict__ Asrc_l =
        is_l1 ? (half ? g_m2l : g_f1l) : (half ? g_m1l : g_f0l);
    const __nv_bfloat16* __restrict__ Wh = g_w1h + half * 32768;
    const __nv_bfloat16* __restrict__ Wl = g_w1l + half * 32768;
    const float* __restrict__ bias = half ? bn1 : bx1;

    const int ar = tid >> 2, k0e = (tid & 3) * 16;     // A copy mapping
    const int krow = tid >> 2, n0 = (tid & 3) * 32;    // B copy mapping

    auto load_chunk = [&](int c, int s) {
        char* AhS = base + s * L1_SET;
        char* AlS = AhS + L1_ASZ;
        char* BhS = AlS + L1_ASZ;
        char* BlS = BhS + L1_BSZ;
        size_t asrc = (size_t)(m0 + ar) * DIM + c * 64 + k0e;
        uint32_t ad = (uint32_t)ar * ASTR + (uint32_t)k0e * 2;
        *(uint4*)(AhS + ad)      = __ldg((const uint4*)(Asrc_h + asrc));
        *(uint4*)(AhS + ad + 16) = __ldg((const uint4*)(Asrc_h + asrc + 8));
        *(uint4*)(AlS + ad)      = __ldg((const uint4*)(Asrc_l + asrc));
        *(uint4*)(AlS + ad + 16) = __ldg((const uint4*)(Asrc_l + asrc + 8));
        size_t bsrc = (size_t)(c * 64 + krow) * HIDV + n0;
        uint32_t bd = (uint32_t)krow * BSTR + (uint32_t)n0 * 2;
#pragma unroll
        for (int q = 0; q < 4; ++q) {
            *(uint4*)(BhS + bd + q * 16) = __ldg((const uint4*)(Wh + bsrc + q * 8));
            *(uint4*)(BlS + bd + q * 16) = __ldg((const uint4*)(Wl + bsrc + q * 8));
        }
    };

    const int wm  = (wid & 3) * 16;
    const int wnl = (wid >> 2) * 64;
    float acc[8][4];
#pragma unroll
    for (int nt = 0; nt < 8; ++nt)
#pragma unroll
        for (int i = 0; i < 4; ++i) acc[nt][i] = 0.f;

    auto mma_chunk = [&](int s) {
        uint32_t Ab = sb + s * L1_SET;
        uint32_t Bb = Ab + 2 * L1_ASZ;
#pragma unroll
        for (int ks = 0; ks < 4; ++ks) {
            const int k0 = ks * 16;
            uint32_t ah[4], al[4];
            uint32_t ra = Ab + (uint32_t)(wm + (lane & 15)) * ASTR
                        + (uint32_t)(lane >> 4) * 16 + (uint32_t)k0 * 2;
            ldsm4(ah, ra);
            ldsm4(al, ra + L1_ASZ);
            uint32_t bhf[8][2], blf[8][2];
#pragma unroll
            for (int nt = 0; nt < 8; ++nt) {
                uint32_t rb = Bb + (uint32_t)(k0 + (lane & 15)) * BSTR
                            + (uint32_t)(wnl + nt * 8) * 2;
                ldsm2t(bhf[nt], rb);
                ldsm2t(blf[nt], rb + L1_BSZ);
            }
#pragma unroll
            for (int nt = 0; nt < 8; ++nt) mma16816(acc[nt], ah, bhf[nt]);
#pragma unroll
            for (int nt = 0; nt < 8; ++nt) mma16816(acc[nt], ah, blf[nt]);
#pragma unroll
            for (int nt = 0; nt < 8; ++nt) mma16816(acc[nt], al, bhf[nt]);
        }
    };

    load_chunk(kz0, 0);
    __syncthreads();
#pragma unroll 1
    for (int ci = 0; ci < nch; ++ci) {
        mma_chunk(ci & 1);
        if (ci + 1 < nch) load_chunk(kz0 + ci + 1, (ci + 1) & 1);
        __syncthreads();
    }

    if (is_l1) {
        // relu + bias -> smem stage -> group-25 column means -> mh1 atomics
        float* ep = (float*)base;      // 64 x 130 fp32
#pragma unroll
        for (int nt = 0; nt < 8; ++nt) {
            int c0 = wnl + nt * 8 + 2 * tg;
            float2 bv = *(const float2*)(bias + c0);
            int r0 = wm + g;
            ep[r0 * 130 + c0]           = fmaxf(acc[nt][0] + bv.x, 0.f);
            ep[r0 * 130 + c0 + 1]       = fmaxf(acc[nt][1] + bv.y, 0.f);
            ep[(r0 + 8) * 130 + c0]     = fmaxf(acc[nt][2] + bv.x, 0.f);
            ep[(r0 + 8) * 130 + c0 + 1] = fmaxf(acc[nt][3] + bv.y, 0.f);
        }
        __syncthreads();
        const int gbase = m0 / 25;
        for (int idx = tid; idx < 4 * 128; idx += 256) {
            int gi = idx >> 7, col = idx & 127;
            int gg = gbase + gi;
            int rs = gg * 25 - m0;      if (rs < 0)  rs = 0;
            int re = gg * 25 + 25 - m0; if (re > 64) re = 64;
            if (rs < re) {
                float s = 0.f;
                for (int r = rs; r < re; ++r) s += ep[r * 130 + col];
                atomicAdd(&g_acc[(size_t)gg * DIM + half * HIDV + col], s * (1.f / 25.f));
            }
        }
    } else {
        float* h0p = g_acc + NB * DIM;
#pragma unroll
        for (int nt = 0; nt < 8; ++nt) {
            int c0 = wnl + nt * 8 + 2 * tg;
            float bvx = 0.f, bvy = 0.f;
            if (kz0 == 0) { float2 bv = *(const float2*)(bias + c0); bvx = bv.x; bvy = bv.y; }
            int r0 = m0 + wm + g;
            float* d0 = &h0p[(size_t)r0 * DIM + half * HIDV + c0];
            atomicAdd(d0,     acc[nt][0] + bvx);
            atomicAdd(d0 + 1, acc[nt][1] + bvy);
            float* d1 = &h0p[(size_t)(r0 + 8) * DIM + half * HIDV + c0];
            atomicAdd(d1,     acc[nt][2] + bvx);
            atomicAdd(d1 + 1, acc[nt][3] + bvy);
        }
    }
}

// ---------------------------------------------------------------------------
// K3: g0 = [relu(h0)@Wx2+bx2 ; mh1@Wn2+bn2], split-K (8,2,4).
// ---------------------------------------------------------------------------
__global__ __launch_bounds__(256)
void g0_kernel(const float* __restrict__ bx2, const float* __restrict__ bn2)
{
    extern __shared__ char smraw[];
    uint32_t raw = smem_u32(smraw);
    uint32_t sb  = (raw + 255) & ~255u;
    char* base   = smraw + (sb - raw);
    char* AhS = base;
    char* AlS = AhS + L1_ASZ;
    char* BhS = AlS + L1_ASZ;
    char* BlS = BhS + L1_BSZ;

    const int tid = threadIdx.x, wid = tid >> 5, lane = tid & 31;
    const int g = lane >> 2, tg = lane & 3;
    const int m0 = blockIdx.x * 64;
    const int half = blockIdx.y;
    const int kz   = blockIdx.z;
    const float* __restrict__ Asrc = half ? g_acc : (g_acc + NB * DIM); // mh1 : h0
    const __nv_bfloat16* __restrict__ Wh = g_w2h + half * 32768;
    const __nv_bfloat16* __restrict__ Wl = g_w2l + half * 32768;
    const float* __restrict__ bias = half ? bn2 : bx2;

    {   // A: fp32 -> split (relu for half 0)
        const int ar = tid >> 2, k0e = (tid & 3) * 16;
        const float4* p = (const float4*)(Asrc + (size_t)(m0 + ar) * DIM + kz * 64 + k0e);
#pragma unroll
        for (int q = 0; q < 4; ++q) {
            float4 v = __ldg(p + q);
            if (half == 0) {
                v.x = fmaxf(v.x, 0.f); v.y = fmaxf(v.y, 0.f);
                v.z = fmaxf(v.z, 0.f); v.w = fmaxf(v.w, 0.f);
            }
            uint32_t o = (uint32_t)ar * ASTR + (uint32_t)(k0e + q * 4) * 2;
            split_store(AhS + o, AlS + o, v);
        }
    }
    {   // B: pure copies
        const int krow = tid >> 2, n0 = (tid & 3) * 32;
        size_t bsrc = (size_t)(kz * 64 + krow) * HIDV + n0;
        uint32_t bd = (uint32_t)krow * BSTR + (uint32_t)n0 * 2;
#pragma unroll
        for (int q = 0; q < 4; ++q) {
            *(uint4*)(BhS + bd + q * 16) = __ldg((const uint4*)(Wh + bsrc + q * 8));
            *(uint4*)(BlS + bd + q * 16) = __ldg((const uint4*)(Wl + bsrc + q * 8));
        }
    }
    __syncthreads();

    const int wm  = (wid & 3) * 16;
    const int wnl = (wid >> 2) * 64;
    float acc[8][4];
#pragma unroll
    for (int nt = 0; nt < 8; ++nt)
#pragma unroll
        for (int i = 0; i < 4; ++i) acc[nt][i] = 0.f;

    const uint32_t Ab = sb, Bb = sb + 2 * L1_ASZ;
#pragma unroll
    for (int ks = 0; ks < 4; ++ks) {
        const int k0 = ks * 16;
        uint32_t ah[4], al[4];
        uint32_t ra = Ab + (uint32_t)(wm + (lane & 15)) * ASTR
                    + (uint32_t)(lane >> 4) * 16 + (uint32_t)k0 * 2;
        ldsm4(ah, ra);
        ldsm4(al, ra + L1_ASZ);
        uint32_t bhf[8][2], blf[8][2];
#pragma unroll
        for (int nt = 0; nt < 8; ++nt) {
            uint32_t rb = Bb + (uint32_t)(k0 + (lane & 15)) * BSTR
                        + (uint32_t)(wnl + nt * 8) * 2;
            ldsm2t(bhf[nt], rb);
            ldsm2t(blf[nt], rb + L1_BSZ);
        }
#pragma unroll
        for (int nt = 0; nt < 8; ++nt) mma16816(acc[nt], ah, bhf[nt]);
#pragma unroll
        for (int nt = 0; nt < 8; ++nt) mma16816(acc[nt], ah, blf[nt]);
#pragma unroll
        for (int nt = 0; nt < 8; ++nt) mma16816(acc[nt], al, bhf[nt]);
    }

    float* g0p = g_acc + 2 * NB * DIM;
#pragma unroll
    for (int nt = 0; nt < 8; ++nt) {
        int c0 = wnl + nt * 8 + 2 * tg;
        float bvx = 0.f, bvy = 0.f;
        if (kz == 0) { float2 bv = *(const float2*)(bias + c0); bvx = bv.x; bvy = bv.y; }
        int r0 = m0 + wm + g;
        float* d0 = &g0p[(size_t)r0 * DIM + half * HIDV + c0];
        atomicAdd(d0,     acc[nt][0] + bvx);
        atomicAdd(d0 + 1, acc[nt][1] + bvy);
        float* d1 = &g0p[(size_t)(r0 + 8) * DIM + half * HIDV + c0];
        atomicAdd(d1,     acc[nt][2] + bvx);
        atomicAdd(d1 + 1, acc[nt][3] + bvy);
    }
}

// ---------------------------------------------------------------------------
// K4: row-normalize g0 then FC [256 -> 7].
// ---------------------------------------------------------------------------
__global__ __launch_bounds__(256)
void final_kernel(const float* __restrict__ Wfc, const float* __restrict__ bfc,
                  float* __restrict__ out)
{
    const int row = blockIdx.x;
    __shared__ float s[DIM];
    __shared__ float red[8];
    __shared__ float s_inv;
    const int t = threadIdx.x;
    const float* g0p = g_acc + 2 * NB * DIM;

    float v = g0p[(size_t)row * DIM + t];
    s[t] = v;
    float sq = v * v;
#pragma unroll
    for (int o = 16; o; o >>= 1) sq += __shfl_xor_sync(0xFFFFFFFFu, sq, o);
    if ((t & 31) == 0) red[t >> 5] = sq;
    __syncthreads();
    if (t == 0) {
        float tot = 0.f;
#pragma unroll
        for (int i = 0; i < 8; ++i) tot += red[i];
        s_inv = 1.f / fmaxf(sqrtf(tot), 1e-12f);
    }
    __syncthreads();
    const float inv = s_inv;

    const int w = t >> 5, l = t & 31;
    if (w < 7) {
        float acc = 0.f;
#pragma unroll
        for (int k = l; k < DIM; k += 32)
            acc = fmaf(s[k], __ldg(&Wfc[k * 7 + w]), acc);
#pragma unroll
        for (int o = 16; o; o >>= 1) acc += __shfl_xor_sync(0xFFFFFFFFu, acc, o);
        if (l == 0) out[row * 7 + w] = acc * inv + bfc[w];
    }
}

// ---------------------------------------------------------------------------
extern "C" void kernel_launch(void* const* d_in, const int* in_sizes, int n_in,
                              void* d_out, int out_size)
{
    const int*   ids   = (const int*)  d_in[0];
    const int*   ids1  = (const int*)  d_in[1];
    const int*   ids2  = (const int*)  d_in[2];
    const float* feats = (const float*)d_in[3];
    const float* Wx1   = (const float*)d_in[4];
    const float* bx1   = (const float*)d_in[5];
    const float* Wn1   = (const float*)d_in[6];
    const float* bn1   = (const float*)d_in[7];
    const float* Wx2   = (const float*)d_in[8];
    const float* bx2   = (const float*)d_in[9];
    const float* Wn2   = (const float*)d_in[10];
    const float* bn2   = (const float*)d_in[11];
    const float* Wfc   = (const float*)d_in[12];
    const float* bfc   = (const float*)d_in[13];
    float* out = (float*)d_out;

    cudaFuncSetAttribute(k2_kernel, cudaFuncAttributeMaxDynamicSharedMemorySize, SM_K2);
    cudaFuncSetAttribute(g0_kernel, cudaFuncAttributeMaxDynamicSharedMemorySize, SM_K3);

    // K1: all gathers/means/splits + zeroing
    prep_kernel<<<3416, 256>>>(feats, ids, ids1, ids2, Wx1, Wn1, Wx2, Wn2);
    // K2: l1 GEMM (-> mh1) + h0 GEMM (merged)
    k2_kernel<<<464, 256, SM_K2>>>(bx1, bn1);
    // K3: g0 GEMM
    g0_kernel<<<dim3(8, 2, 4), 256, SM_K3>>>(bx2, bn2);
    // K4: normalize + FC
    final_kernel<<<NB, 256>>>(Wfc, bfc, out);
}